// round 2
// baseline (speedup 1.0000x reference)
#include <cuda_runtime.h>
#include <math.h>
#include <float.h>

#define S_    3000
#define F_    6
#define N_    128
#define L_    40
#define LMAX_ 10
#define K_    5
#define SL_   (S_*LMAX_)   // 30000

// ---------------- scratch (device globals; no allocations allowed) ----------
__device__ float g_WhhT[N_*4*N_];        // [128][512] k-major transpose of Whh
__device__ float g_Hln[SL_*N_];          // [30000][128] layernormed H, t in [30,40)
__device__ float g_Hk [SL_*N_];          // l2norm(Hln @ WK^T)
__device__ float g_q  [S_*N_];           // l2norm(Hln[tgt,9] @ WQ^T)
__device__ float g_pval[S_*20];          // 4 splits x top5 per target
__device__ int   g_pidx[S_*20];

__device__ __forceinline__ float sigf(float x){ return 1.f/(1.f+__expf(-x)); }
__device__ __forceinline__ float tanhfast(float x){ return 2.f/(1.f+__expf(-2.f*x)) - 1.f; }
__device__ __forceinline__ bool better(float v,int i,float bv,int bi){
    return (v>bv) || (v==bv && i<bi);
}

// ---------------- kernel 0: transpose Whh [512][128] -> [128][512] ----------
__global__ void __launch_bounds__(256) transpose_whh(const float* __restrict__ Whh){
    int idx = blockIdx.x*256 + threadIdx.x;          // 65536 elements
    if (idx < 512*128){
        int j = idx >> 7, k = idx & 127;
        g_WhhT[k*512 + j] = Whh[idx];
    }
}

// ---------------- kernel 1: LSTM (+ fused LayerNorm for t>=30) --------------
// 8 stocks per block, 256 threads. Thread owns 2 gate columns for GEMM phase,
// and 4 (stock,unit) states (warp w <-> stock w) for the update/LN phase.
__global__ void __launch_bounds__(256) lstm_kernel(
    const float* __restrict__ X,   const float* __restrict__ Wih,
    const float* __restrict__ bih, const float* __restrict__ bhh,
    const float* __restrict__ lng, const float* __restrict__ lnb)
{
    __shared__ float sh[8][128];      // hidden state
    __shared__ float sg[8][512];      // gates
    __shared__ float sx[8][240];      // x for 40 steps * 6 feats
    const int tid = threadIdx.x;
    const int bs0 = blockIdx.x*8;

    for (int idx=tid; idx<8*240; idx+=256)
        sx[idx/240][idx%240] = X[(bs0 + idx/240)*240 + idx%240];
    for (int idx=tid; idx<1024; idx+=256) ((float*)sh)[idx] = 0.f;

    const int j0 = tid*2;
    float wih0[6], wih1[6];
    #pragma unroll
    for (int f=0; f<6; f++){ wih0[f]=Wih[j0*6+f]; wih1[f]=Wih[j0*6+6+f]; }
    const float bb0 = bih[j0]+bhh[j0];
    const float bb1 = bih[j0+1]+bhh[j0+1];

    const int su = tid>>5;             // stock for update phase (warp id)
    const int n0 = (tid&31)*4;         // unit base
    float c0=0.f,c1=0.f,c2=0.f,c3=0.f;
    const float4 g4 = *(const float4*)&lng[n0];
    const float4 b4 = *(const float4*)&lnb[n0];

    for (int t=0; t<40; t++){
        __syncthreads();
        float a0[8], a1[8];
        #pragma unroll
        for (int s=0;s<8;s++){ a0[s]=bb0; a1[s]=bb1; }
        #pragma unroll
        for (int f=0;f<6;f++){
            float w0=wih0[f], w1=wih1[f];
            #pragma unroll
            for (int s=0;s<8;s++){ float xv=sx[s][t*6+f]; a0[s]+=xv*w0; a1[s]+=xv*w1; }
        }
        #pragma unroll 2
        for (int k=0;k<128;k+=4){
            float2 w0 = *(const float2*)&g_WhhT[(k+0)*512 + j0];
            float2 w1 = *(const float2*)&g_WhhT[(k+1)*512 + j0];
            float2 w2 = *(const float2*)&g_WhhT[(k+2)*512 + j0];
            float2 w3 = *(const float2*)&g_WhhT[(k+3)*512 + j0];
            #pragma unroll
            for (int s=0;s<8;s++){
                float4 hv = *(const float4*)&sh[s][k];
                a0[s] += hv.x*w0.x; a0[s] += hv.y*w1.x; a0[s] += hv.z*w2.x; a0[s] += hv.w*w3.x;
                a1[s] += hv.x*w0.y; a1[s] += hv.y*w1.y; a1[s] += hv.z*w2.y; a1[s] += hv.w*w3.y;
            }
        }
        #pragma unroll
        for (int s=0;s<8;s++){ sg[s][j0]=a0[s]; sg[s][j0+1]=a1[s]; }
        __syncthreads();

        float4 gi = *(const float4*)&sg[su][n0];
        float4 gf = *(const float4*)&sg[su][128+n0];
        float4 gg = *(const float4*)&sg[su][256+n0];
        float4 go = *(const float4*)&sg[su][384+n0];
        c0 = sigf(gf.x)*c0 + sigf(gi.x)*tanhfast(gg.x);
        c1 = sigf(gf.y)*c1 + sigf(gi.y)*tanhfast(gg.y);
        c2 = sigf(gf.z)*c2 + sigf(gi.z)*tanhfast(gg.z);
        c3 = sigf(gf.w)*c3 + sigf(gi.w)*tanhfast(gg.w);
        float4 h4;
        h4.x = sigf(go.x)*tanhfast(c0);
        h4.y = sigf(go.y)*tanhfast(c1);
        h4.z = sigf(go.z)*tanhfast(c2);
        h4.w = sigf(go.w)*tanhfast(c3);
        *(float4*)&sh[su][n0] = h4;

        if (t >= 30){
            float sum = h4.x+h4.y+h4.z+h4.w;
            float ssq = h4.x*h4.x+h4.y*h4.y+h4.z*h4.z+h4.w*h4.w;
            #pragma unroll
            for (int o=16;o>=1;o>>=1){
                sum += __shfl_xor_sync(0xffffffffu, sum, o);
                ssq += __shfl_xor_sync(0xffffffffu, ssq, o);
            }
            float mean = sum*(1.f/128.f);
            float var  = ssq*(1.f/128.f) - mean*mean;
            float rstd = rsqrtf(var + 1e-5f);
            float4 o4;
            o4.x = (h4.x-mean)*rstd*g4.x + b4.x;
            o4.y = (h4.y-mean)*rstd*g4.y + b4.y;
            o4.z = (h4.z-mean)*rstd*g4.z + b4.z;
            o4.w = (h4.w-mean)*rstd*g4.w + b4.w;
            *(float4*)&g_Hln[((bs0+su)*10 + (t-30))*128 + n0] = o4;
        }
    }
}

// ---------------- kernel 2: projection + row l2norm ------------------------
// out[r] = l2norm(A[r] @ W^T), A row = g_Hln[src]; src gathered for q.
// which==0 -> g_Hk (rows=30000, no gather), which==1 -> g_q (rows=3000, gather)
__global__ void __launch_bounds__(256) proj_kernel(
    const float* __restrict__ W, const int* __restrict__ gatherIdx,
    int nrows, int which)
{
    __shared__ float sA [32*129];
    __shared__ float sWt[32*132];      // transposed k-chunk of W
    __shared__ float sred[32][8];
    float* out = which ? g_q : g_Hk;

    const int tid = threadIdx.x;
    const int r0  = blockIdx.x*32;

    for (int idx=tid; idx<4096; idx+=256){
        int r = idx>>7, k = idx&127;
        int gr = r0 + r;
        float v = 0.f;
        if (gr < nrows){
            int src = gatherIdx ? (gatherIdx[gr]*10 + 9) : gr;
            v = g_Hln[src*128 + k];
        }
        sA[r*129 + k] = v;
    }

    const int r  = tid>>3;
    const int cg = tid&7;
    float acc[16];
    #pragma unroll
    for (int m=0;m<16;m++) acc[m]=0.f;

    for (int kc=0; kc<4; kc++){
        __syncthreads();
        for (int idx=tid; idx<4096; idx+=256){
            int kk = idx&31, j = idx>>5;
            sWt[kk*132 + j] = W[j*128 + kc*32 + kk];
        }
        __syncthreads();
        const float* arow = &sA[r*129 + kc*32];
        for (int kk=0; kk<32; kk++){
            float a = arow[kk];
            const float* wr = &sWt[kk*132 + cg*16];
            #pragma unroll
            for (int m=0;m<16;m+=4){
                float4 w4 = *(const float4*)&wr[m];
                acc[m]  +=a*w4.x; acc[m+1]+=a*w4.y; acc[m+2]+=a*w4.z; acc[m+3]+=a*w4.w;
            }
        }
    }
    float ss=0.f;
    #pragma unroll
    for (int m=0;m<16;m++) ss += acc[m]*acc[m];
    sred[r][cg]=ss;
    __syncthreads();
    float tot=0.f;
    #pragma unroll
    for (int g=0; g<8; g++) tot += sred[r][g];
    float inv = 1.f/fmaxf(sqrtf(tot), 1e-12f);

    int gr = r0 + r;
    if (gr < nrows){
        #pragma unroll
        for (int m=0;m<16;m+=4){
            float4 o;
            o.x=acc[m]*inv; o.y=acc[m+1]*inv; o.z=acc[m+2]*inv; o.w=acc[m+3]*inv;
            *(float4*)&out[gr*128 + cg*16 + m] = o;
        }
    }
}

// ---------------- kernel 3: attention GEMM + fused top-5 -------------------
// grid (94 target tiles, 4 column splits); 32 targets/block, 8 threads/target.
__global__ void __launch_bounds__(256) attn_kernel(
    const float* __restrict__ log_temp, const float* __restrict__ lag_bias,
    const int*   __restrict__ target_idx)
{
    __shared__ float sq[32*132];
    __shared__ float sH[32*132];
    __shared__ float sv[32][40];
    __shared__ int   si[32][40];
    __shared__ float slb[10];
    const int tid = threadIdx.x;
    const int tl  = tid>>3, g = tid&7;
    const int tgt = blockIdx.x*32 + tl;

    if (tid<10) slb[tid]=lag_bias[tid];
    for (int idx=tid; idx<4096; idx+=256){
        int r=idx>>7, k=idx&127;
        int gt = blockIdx.x*32 + r;
        sq[r*132+k] = (gt<S_) ? g_q[gt*128+k] : 0.f;
    }
    float invtemp;
    { float tp=__expf(log_temp[0]); tp=fminf(fmaxf(tp,0.1f),11.313708498984761f); invtemp=1.f/tp; }
    const int mystock = (tgt<S_) ? target_idx[tgt] : -1;

    float tv[5]; int ti[5];
    #pragma unroll
    for (int m=0;m<5;m++){ tv[m]=-FLT_MAX; ti[m]=0x7fffffff; }

    const int cstart = blockIdx.y*235;
    const int cend   = min(cstart+235, 938);   // 938 chunks of 32 cols
    for (int ch=cstart; ch<cend; ch++){
        const int c0 = ch*32;
        __syncthreads();
        for (int idx=tid; idx<4096; idx+=256){
            int r=idx>>7, k=idx&127;
            int col=c0+r;
            sH[r*132+k] = (col<SL_) ? g_Hk[col*128+k] : 0.f;
        }
        __syncthreads();
        for (int cc=g; cc<32; cc+=8){
            int col = c0+cc;
            if (col >= SL_) break;
            int s = col/10;
            if (s == mystock) continue;
            int l = col - s*10;
            const float* qr=&sq[tl*132];
            const float* hr=&sH[cc*132];
            float acc=0.f;
            #pragma unroll
            for (int k=0;k<128;k+=4){
                float4 qv=*(const float4*)&qr[k];
                float4 hv=*(const float4*)&hr[k];
                acc += qv.x*hv.x; acc += qv.y*hv.y; acc += qv.z*hv.z; acc += qv.w*hv.w;
            }
            float val = acc*invtemp + slb[l];
            if (better(val,col,tv[4],ti[4])){
                tv[4]=val; ti[4]=col;
                #pragma unroll
                for (int p=4;p>0;p--){
                    if (better(tv[p],ti[p],tv[p-1],ti[p-1])){
                        float tvv=tv[p]; tv[p]=tv[p-1]; tv[p-1]=tvv;
                        int   tii=ti[p]; ti[p]=ti[p-1]; ti[p-1]=tii;
                    }
                }
            }
        }
    }
    __syncthreads();
    #pragma unroll
    for (int m=0;m<5;m++){ sv[tl][g*5+m]=tv[m]; si[tl][g*5+m]=ti[m]; }
    __syncthreads();
    if (g==0 && tgt<S_){
        for (int kk=0;kk<5;kk++){
            float bv=-FLT_MAX; int bi=0x7fffffff; int bp=0;
            for (int m=0;m<40;m++){
                float v=sv[tl][m]; int ii=si[tl][m];
                if (better(v,ii,bv,bi)){ bv=v; bi=ii; bp=m; }
            }
            g_pval[tgt*20 + blockIdx.y*5 + kk]=bv;
            g_pidx[tgt*20 + blockIdx.y*5 + kk]=bi;
            sv[tl][bp]=-FLT_MAX; si[tl][bp]=0x7fffffff;
        }
    }
}

// ---------------- kernel 4: merge + softmax + gather + MLP -----------------
__global__ void __launch_bounds__(256) final_kernel(
    const float* __restrict__ Xraw,
    const float* __restrict__ W1, const float* __restrict__ b1,
    const float* __restrict__ W2, const float* __restrict__ b2,
    const float* __restrict__ W3, const float* __restrict__ b3,
    float* __restrict__ out)
{
    int t = blockIdx.x*256 + threadIdx.x;
    if (t >= S_) return;
    float cv[20]; int ci[20];
    #pragma unroll
    for (int m=0;m<20;m++){ cv[m]=g_pval[t*20+m]; ci[m]=g_pidx[t*20+m]; }
    float v5[5]; int i5[5];
    #pragma unroll
    for (int kk=0;kk<5;kk++){
        float bv=-FLT_MAX; int bi=0x7fffffff; int bp=0;
        #pragma unroll
        for (int m=0;m<20;m++)
            if (better(cv[m],ci[m],bv,bi)){ bv=cv[m]; bi=ci[m]; bp=m; }
        v5[kk]=bv; i5[kk]=bi;
        cv[bp]=-FLT_MAX; ci[bp]=0x7fffffff;
    }
    float w[5]; float den=0.f;
    #pragma unroll
    for (int kk=0;kk<5;kk++){ w[kk]=__expf(v5[kk]-v5[0]); den+=w[kk]; }
    float invden = 1.f/den;
    float feat[12];
    float zagg[6] = {0,0,0,0,0,0};
    #pragma unroll
    for (int kk=0;kk<5;kk++){
        int idx = i5[kk];
        int leader = idx/10;
        int lag    = idx - leader*10;
        int pos    = 29 + lag;
        const float* zp = &Xraw[(leader*40 + pos)*6];
        float ww = w[kk]*invden;
        #pragma unroll
        for (int f=0;f<6;f++){
            float zf = zp[f];
            zagg[f] += ww*zf;
            if (kk==0) feat[6+f]=zf;
        }
    }
    #pragma unroll
    for (int f=0;f<6;f++) feat[f]=zagg[f];

    float h1[64];
    #pragma unroll
    for (int j=0;j<64;j++){
        float a = b1[j];
        #pragma unroll
        for (int f=0;f<12;f++) a += W1[j*12+f]*feat[f];
        h1[j] = fmaxf(a,0.f);
    }
    float h2[32];
    #pragma unroll
    for (int j=0;j<32;j++){
        float a = b2[j];
        #pragma unroll
        for (int f=0;f<64;f++) a += W2[j*64+f]*h1[f];
        h2[j] = fmaxf(a,0.f);
    }
    float a = b3[0];
    #pragma unroll
    for (int j=0;j<32;j++) a += W3[j]*h2[j];
    out[t] = a;
}

// ---------------- launch ----------------------------------------------------
extern "C" void kernel_launch(void* const* d_in, const int* in_sizes, int n_in,
                              void* d_out, int out_size)
{
    const float* Xs  =(const float*)d_in[0];
    const float* Xr  =(const float*)d_in[1];
    const int*   tgt =(const int*)  d_in[2];
    const float* Wih =(const float*)d_in[3];
    const float* Whh =(const float*)d_in[4];
    const float* bihp=(const float*)d_in[5];
    const float* bhhp=(const float*)d_in[6];
    const float* lng =(const float*)d_in[7];
    const float* lnb =(const float*)d_in[8];
    const float* WQ  =(const float*)d_in[9];
    const float* WK  =(const float*)d_in[10];
    const float* logt=(const float*)d_in[11];
    const float* lagb=(const float*)d_in[12];
    const float* W1  =(const float*)d_in[13];
    const float* b1  =(const float*)d_in[14];
    const float* W2  =(const float*)d_in[15];
    const float* b2  =(const float*)d_in[16];
    const float* W3  =(const float*)d_in[17];
    const float* b3  =(const float*)d_in[18];
    float* out = (float*)d_out;

    transpose_whh<<<256,256>>>(Whh);
    lstm_kernel<<<375,256>>>(Xs, Wih, bihp, bhhp, lng, lnb);
    proj_kernel<<<938,256>>>(WK, nullptr, SL_, 0);   // -> g_Hk
    proj_kernel<<<94, 256>>>(WQ, tgt,     S_,  1);   // -> g_q
    attn_kernel<<<dim3(94,4),256>>>(logt, lagb, tgt);
    final_kernel<<<12,256>>>(Xr, W1,b1, W2,b2, W3,b3, out);
}

// round 3
// speedup vs baseline: 1.6119x; 1.6119x over previous
#include <cuda_runtime.h>
#include <math.h>
#include <float.h>

#define S_    3000
#define F_    6
#define N_    128
#define L_    40
#define LMAX_ 10
#define K_    5
#define SL_   (S_*LMAX_)   // 30000
#define NTILE_ 469         // ceil(30000/64)
#define NSPLIT_ 8
#define TILES_PER_SPLIT_ 59

// ---------------- scratch (device globals; no allocations allowed) ----------
__device__ float g_WhhT[N_*4*N_];        // [128][512] k-major transpose of Whh
__device__ float g_Hln[SL_*N_];          // [30000][128] layernormed H, t in [30,40)
__device__ float g_Hk [SL_*N_];          // l2norm(Hln @ WK^T)
__device__ float g_q  [S_*N_];           // l2norm(Hln[tgt,9] @ WQ^T)
__device__ float g_pval[S_*40];          // 8 splits x top5 per target
__device__ int   g_pidx[S_*40];

__device__ __forceinline__ float sigf(float x){ return 1.f/(1.f+__expf(-x)); }
__device__ __forceinline__ float tanhfast(float x){ return 2.f/(1.f+__expf(-2.f*x)) - 1.f; }
__device__ __forceinline__ bool better(float v,int i,float bv,int bi){
    return (v>bv) || (v==bv && i<bi);
}

// ---------------- kernel 0: transpose Whh [512][128] -> [128][512] ----------
__global__ void __launch_bounds__(256) transpose_whh(const float* __restrict__ Whh){
    int idx = blockIdx.x*256 + threadIdx.x;          // 65536 elements
    if (idx < 512*128){
        int j = idx >> 7, k = idx & 127;
        g_WhhT[k*512 + j] = Whh[idx];
    }
}

// ---------------- kernel 1: LSTM (+ fused LayerNorm for t>=30) --------------
__global__ void __launch_bounds__(256) lstm_kernel(
    const float* __restrict__ X,   const float* __restrict__ Wih,
    const float* __restrict__ bih, const float* __restrict__ bhh,
    const float* __restrict__ lng, const float* __restrict__ lnb)
{
    __shared__ float sh[8][128];      // hidden state
    __shared__ float sg[8][512];      // gates
    __shared__ float sx[8][240];      // x for 40 steps * 6 feats
    const int tid = threadIdx.x;
    const int bs0 = blockIdx.x*8;

    for (int idx=tid; idx<8*240; idx+=256)
        sx[idx/240][idx%240] = X[(bs0 + idx/240)*240 + idx%240];
    for (int idx=tid; idx<1024; idx+=256) ((float*)sh)[idx] = 0.f;

    const int j0 = tid*2;
    float wih0[6], wih1[6];
    #pragma unroll
    for (int f=0; f<6; f++){ wih0[f]=Wih[j0*6+f]; wih1[f]=Wih[j0*6+6+f]; }
    const float bb0 = bih[j0]+bhh[j0];
    const float bb1 = bih[j0+1]+bhh[j0+1];

    const int su = tid>>5;             // stock for update phase (warp id)
    const int n0 = (tid&31)*4;         // unit base
    float c0=0.f,c1=0.f,c2=0.f,c3=0.f;
    const float4 g4 = *(const float4*)&lng[n0];
    const float4 b4 = *(const float4*)&lnb[n0];

    for (int t=0; t<40; t++){
        __syncthreads();
        float a0[8], a1[8];
        #pragma unroll
        for (int s=0;s<8;s++){ a0[s]=bb0; a1[s]=bb1; }
        #pragma unroll
        for (int f=0;f<6;f++){
            float w0=wih0[f], w1=wih1[f];
            #pragma unroll
            for (int s=0;s<8;s++){ float xv=sx[s][t*6+f]; a0[s]+=xv*w0; a1[s]+=xv*w1; }
        }
        #pragma unroll 2
        for (int k=0;k<128;k+=4){
            float2 w0 = *(const float2*)&g_WhhT[(k+0)*512 + j0];
            float2 w1 = *(const float2*)&g_WhhT[(k+1)*512 + j0];
            float2 w2 = *(const float2*)&g_WhhT[(k+2)*512 + j0];
            float2 w3 = *(const float2*)&g_WhhT[(k+3)*512 + j0];
            #pragma unroll
            for (int s=0;s<8;s++){
                float4 hv = *(const float4*)&sh[s][k];
                a0[s] += hv.x*w0.x; a0[s] += hv.y*w1.x; a0[s] += hv.z*w2.x; a0[s] += hv.w*w3.x;
                a1[s] += hv.x*w0.y; a1[s] += hv.y*w1.y; a1[s] += hv.z*w2.y; a1[s] += hv.w*w3.y;
            }
        }
        #pragma unroll
        for (int s=0;s<8;s++){ sg[s][j0]=a0[s]; sg[s][j0+1]=a1[s]; }
        __syncthreads();

        float4 gi = *(const float4*)&sg[su][n0];
        float4 gf = *(const float4*)&sg[su][128+n0];
        float4 gg = *(const float4*)&sg[su][256+n0];
        float4 go = *(const float4*)&sg[su][384+n0];
        c0 = sigf(gf.x)*c0 + sigf(gi.x)*tanhfast(gg.x);
        c1 = sigf(gf.y)*c1 + sigf(gi.y)*tanhfast(gg.y);
        c2 = sigf(gf.z)*c2 + sigf(gi.z)*tanhfast(gg.z);
        c3 = sigf(gf.w)*c3 + sigf(gi.w)*tanhfast(gg.w);
        float4 h4;
        h4.x = sigf(go.x)*tanhfast(c0);
        h4.y = sigf(go.y)*tanhfast(c1);
        h4.z = sigf(go.z)*tanhfast(c2);
        h4.w = sigf(go.w)*tanhfast(c3);
        *(float4*)&sh[su][n0] = h4;

        if (t >= 30){
            float sum = h4.x+h4.y+h4.z+h4.w;
            float ssq = h4.x*h4.x+h4.y*h4.y+h4.z*h4.z+h4.w*h4.w;
            #pragma unroll
            for (int o=16;o>=1;o>>=1){
                sum += __shfl_xor_sync(0xffffffffu, sum, o);
                ssq += __shfl_xor_sync(0xffffffffu, ssq, o);
            }
            float mean = sum*(1.f/128.f);
            float var  = ssq*(1.f/128.f) - mean*mean;
            float rstd = rsqrtf(var + 1e-5f);
            float4 o4;
            o4.x = (h4.x-mean)*rstd*g4.x + b4.x;
            o4.y = (h4.y-mean)*rstd*g4.y + b4.y;
            o4.z = (h4.z-mean)*rstd*g4.z + b4.z;
            o4.w = (h4.w-mean)*rstd*g4.w + b4.w;
            *(float4*)&g_Hln[((bs0+su)*10 + (t-30))*128 + n0] = o4;
        }
    }
}

// ---------------- kernel 2: projection + row l2norm ------------------------
__global__ void __launch_bounds__(256) proj_kernel(
    const float* __restrict__ W, const int* __restrict__ gatherIdx,
    int nrows, int which)
{
    __shared__ float sA [32*129];
    __shared__ float sWt[32*132];      // transposed k-chunk of W
    __shared__ float sred[32][8];
    float* out = which ? g_q : g_Hk;

    const int tid = threadIdx.x;
    const int r0  = blockIdx.x*32;

    for (int idx=tid; idx<4096; idx+=256){
        int r = idx>>7, k = idx&127;
        int gr = r0 + r;
        float v = 0.f;
        if (gr < nrows){
            int src = gatherIdx ? (gatherIdx[gr]*10 + 9) : gr;
            v = g_Hln[src*128 + k];
        }
        sA[r*129 + k] = v;
    }

    const int r  = tid>>3;
    const int cg = tid&7;
    float acc[16];
    #pragma unroll
    for (int m=0;m<16;m++) acc[m]=0.f;

    for (int kc=0; kc<4; kc++){
        __syncthreads();
        for (int idx=tid; idx<4096; idx+=256){
            int kk = idx&31, j = idx>>5;
            sWt[kk*132 + j] = W[j*128 + kc*32 + kk];
        }
        __syncthreads();
        const float* arow = &sA[r*129 + kc*32];
        for (int kk=0; kk<32; kk++){
            float a = arow[kk];
            const float* wr = &sWt[kk*132 + cg*16];
            #pragma unroll
            for (int m=0;m<16;m+=4){
                float4 w4 = *(const float4*)&wr[m];
                acc[m]  +=a*w4.x; acc[m+1]+=a*w4.y; acc[m+2]+=a*w4.z; acc[m+3]+=a*w4.w;
            }
        }
    }
    float ss=0.f;
    #pragma unroll
    for (int m=0;m<16;m++) ss += acc[m]*acc[m];
    sred[r][cg]=ss;
    __syncthreads();
    float tot=0.f;
    #pragma unroll
    for (int g=0; g<8; g++) tot += sred[r][g];
    float inv = 1.f/fmaxf(sqrtf(tot), 1e-12f);

    int gr = r0 + r;
    if (gr < nrows){
        #pragma unroll
        for (int m=0;m<16;m+=4){
            float4 o;
            o.x=acc[m]*inv; o.y=acc[m+1]*inv; o.z=acc[m+2]*inv; o.w=acc[m+3]*inv;
            *(float4*)&out[gr*128 + cg*16 + m] = o;
        }
    }
}

// ---------------- kernel 3: register-tiled attention GEMM + fused top-5 ----
// Block: 64 targets x 64 cols per tile, 256 threads (16x16), thread = 4x4.
// grid (47 row tiles, 8 col splits). Dynamic smem: sAT[128][68] + sB[64][128].
__global__ void __launch_bounds__(256) attn2_kernel(
    const float* __restrict__ log_temp, const float* __restrict__ lag_bias,
    const int*   __restrict__ target_idx)
{
    extern __shared__ float smem[];
    float* sAT = smem;               // [128][68]  k-major A
    float* sB  = smem + 128*68;      // [64][128]  swizzled B tile
    __shared__ float slb[10];
    __shared__ float sinvt;

    const int tid = threadIdx.x;
    const int tx  = tid & 15, ty = tid >> 4;
    const int rbase = blockIdx.x*64;

    if (tid < 10) slb[tid] = lag_bias[tid];
    if (tid == 0){
        float tp = __expf(log_temp[0]);
        tp = fminf(fmaxf(tp, 0.1f), 11.313708498984761f);
        sinvt = 1.f/tp;
    }

    // Load A tile (64 rows x 128 k), store k-major
    for (int idx = tid; idx < 64*32; idx += 256){
        int row = idx >> 5, kq = idx & 31;
        int gr = rbase + row;
        float4 v = make_float4(0.f,0.f,0.f,0.f);
        if (gr < S_) v = *(const float4*)&g_q[gr*128 + kq*4];
        sAT[(kq*4+0)*68 + row] = v.x;
        sAT[(kq*4+1)*68 + row] = v.y;
        sAT[(kq*4+2)*68 + row] = v.z;
        sAT[(kq*4+3)*68 + row] = v.w;
    }

    int myst[4];
    #pragma unroll
    for (int i=0;i<4;i++){
        int gr = rbase + ty*4 + i;
        myst[i] = (gr < S_) ? target_idx[gr] : -1;
    }

    float tv[4][5]; int ti[4][5];
    #pragma unroll
    for (int r=0;r<4;r++)
        #pragma unroll
        for (int p=0;p<5;p++){ tv[r][p] = -FLT_MAX; ti[r][p] = 0x7fffffff; }

    __syncthreads();
    const float invt = sinvt;
    const int swz = tx & 7;
    const int tstart = blockIdx.y*TILES_PER_SPLIT_;
    const int tend   = min(tstart+TILES_PER_SPLIT_, NTILE_);

    for (int tile = tstart; tile < tend; tile++){
        const int c0 = tile*64;
        __syncthreads();
        // Load B tile (64 cols x 128 k), row-major + 16B XOR swizzle on k
        for (int idx = tid; idx < 64*32; idx += 256){
            int col = idx >> 5, kq = idx & 31;
            int gc = c0 + col;
            float4 v = make_float4(0.f,0.f,0.f,0.f);
            if (gc < SL_) v = *(const float4*)&g_Hk[gc*128 + kq*4];
            int ks = kq ^ ((col>>2)&7);
            *(float4*)&sB[col*128 + ks*4] = v;
        }
        __syncthreads();

        float acc[4][4];
        #pragma unroll
        for (int r=0;r<4;r++)
            #pragma unroll
            for (int c=0;c<4;c++) acc[r][c]=0.f;

        const float* arow = &sAT[ty*4];
        const float* bbase = &sB[(tx*4)*128];

        #pragma unroll 4
        for (int kb = 0; kb < 32; kb++){
            float4 Af[4];
            Af[0] = *(const float4*)&arow[(kb*4+0)*68];
            Af[1] = *(const float4*)&arow[(kb*4+1)*68];
            Af[2] = *(const float4*)&arow[(kb*4+2)*68];
            Af[3] = *(const float4*)&arow[(kb*4+3)*68];
            const int ks = (kb ^ swz)*4;
            float4 Bf[4];
            Bf[0] = *(const float4*)&bbase[0*128 + ks];
            Bf[1] = *(const float4*)&bbase[1*128 + ks];
            Bf[2] = *(const float4*)&bbase[2*128 + ks];
            Bf[3] = *(const float4*)&bbase[3*128 + ks];
            const float* av = (const float*)Af;   // av[k*4 + r]
            const float* bv = (const float*)Bf;   // bv[c*4 + k]
            #pragma unroll
            for (int r=0;r<4;r++)
                #pragma unroll
                for (int c=0;c<4;c++)
                    #pragma unroll
                    for (int k=0;k<4;k++)
                        acc[r][c] += av[k*4+r]*bv[c*4+k];
        }

        // scores + top-5 update
        #pragma unroll
        for (int c=0;c<4;c++){
            int gc = c0 + tx*4 + c;
            int s  = gc/10;
            int l  = gc - s*10;
            bool colok = (gc < SL_);
            float lb = slb[l];
            #pragma unroll
            for (int r=0;r<4;r++){
                if (!colok || s == myst[r]) continue;
                float sc = acc[r][c]*invt + lb;
                if (better(sc, gc, tv[r][4], ti[r][4])){
                    tv[r][4]=sc; ti[r][4]=gc;
                    #pragma unroll
                    for (int p=4;p>0;p--){
                        if (better(tv[r][p],ti[r][p],tv[r][p-1],ti[r][p-1])){
                            float tvv=tv[r][p]; tv[r][p]=tv[r][p-1]; tv[r][p-1]=tvv;
                            int   tii=ti[r][p]; ti[r][p]=ti[r][p-1]; ti[r][p-1]=tii;
                        }
                    }
                }
            }
        }
    }

    // Merge 16 partial top-5 lists per row (alias smem over GEMM tiles)
    __syncthreads();
    float* mv = smem;                         // [64][16][5] floats (20KB)
    int*   mi = (int*)(smem + 64*16*5);       // [64][16][5] ints   (20KB)
    #pragma unroll
    for (int r=0;r<4;r++){
        int row = ty*4+r;
        #pragma unroll
        for (int p=0;p<5;p++){
            mv[(row*16+tx)*5+p] = tv[r][p];
            mi[(row*16+tx)*5+p] = ti[r][p];
        }
    }
    __syncthreads();
    if (tid < 64){
        int gr = rbase + tid;
        if (gr < S_){
            float* cv = &mv[tid*80];
            int*   ci = &mi[tid*80];
            for (int kk=0;kk<5;kk++){
                float bv=-FLT_MAX; int bi=0x7fffffff; int bp=0;
                for (int m=0;m<80;m++){
                    if (better(cv[m],ci[m],bv,bi)){ bv=cv[m]; bi=ci[m]; bp=m; }
                }
                g_pval[gr*40 + blockIdx.y*5 + kk]=bv;
                g_pidx[gr*40 + blockIdx.y*5 + kk]=bi;
                cv[bp]=-FLT_MAX; ci[bp]=0x7fffffff;
            }
        }
    }
}

// ---------------- kernel 4: merge + softmax + gather + MLP -----------------
__global__ void __launch_bounds__(256) final_kernel(
    const float* __restrict__ Xraw,
    const float* __restrict__ W1, const float* __restrict__ b1,
    const float* __restrict__ W2, const float* __restrict__ b2,
    const float* __restrict__ W3, const float* __restrict__ b3,
    float* __restrict__ out)
{
    int t = blockIdx.x*256 + threadIdx.x;
    if (t >= S_) return;
    float cv[40]; int ci[40];
    #pragma unroll
    for (int m=0;m<40;m++){ cv[m]=g_pval[t*40+m]; ci[m]=g_pidx[t*40+m]; }
    float v5[5]; int i5[5];
    #pragma unroll
    for (int kk=0;kk<5;kk++){
        float bv=-FLT_MAX; int bi=0x7fffffff; int bp=0;
        #pragma unroll
        for (int m=0;m<40;m++)
            if (better(cv[m],ci[m],bv,bi)){ bv=cv[m]; bi=ci[m]; bp=m; }
        v5[kk]=bv; i5[kk]=bi;
        cv[bp]=-FLT_MAX; ci[bp]=0x7fffffff;
    }
    float w[5]; float den=0.f;
    #pragma unroll
    for (int kk=0;kk<5;kk++){ w[kk]=__expf(v5[kk]-v5[0]); den+=w[kk]; }
    float invden = 1.f/den;
    float feat[12];
    float zagg[6] = {0,0,0,0,0,0};
    #pragma unroll
    for (int kk=0;kk<5;kk++){
        int idx = i5[kk];
        int leader = idx/10;
        int lag    = idx - leader*10;
        int pos    = 29 + lag;
        const float* zp = &Xraw[(leader*40 + pos)*6];
        float ww = w[kk]*invden;
        #pragma unroll
        for (int f=0;f<6;f++){
            float zf = zp[f];
            zagg[f] += ww*zf;
            if (kk==0) feat[6+f]=zf;
        }
    }
    #pragma unroll
    for (int f=0;f<6;f++) feat[f]=zagg[f];

    float h1[64];
    #pragma unroll
    for (int j=0;j<64;j++){
        float a = b1[j];
        #pragma unroll
        for (int f=0;f<12;f++) a += W1[j*12+f]*feat[f];
        h1[j] = fmaxf(a,0.f);
    }
    float h2[32];
    #pragma unroll
    for (int j=0;j<32;j++){
        float a = b2[j];
        #pragma unroll
        for (int f=0;f<64;f++) a += W2[j*64+f]*h1[f];
        h2[j] = fmaxf(a,0.f);
    }
    float a = b3[0];
    #pragma unroll
    for (int j=0;j<32;j++) a += W3[j]*h2[j];
    out[t] = a;
}

// ---------------- launch ----------------------------------------------------
extern "C" void kernel_launch(void* const* d_in, const int* in_sizes, int n_in,
                              void* d_out, int out_size)
{
    const float* Xs  =(const float*)d_in[0];
    const float* Xr  =(const float*)d_in[1];
    const int*   tgt =(const int*)  d_in[2];
    const float* Wih =(const float*)d_in[3];
    const float* Whh =(const float*)d_in[4];
    const float* bihp=(const float*)d_in[5];
    const float* bhhp=(const float*)d_in[6];
    const float* lng =(const float*)d_in[7];
    const float* lnb =(const float*)d_in[8];
    const float* WQ  =(const float*)d_in[9];
    const float* WK  =(const float*)d_in[10];
    const float* logt=(const float*)d_in[11];
    const float* lagb=(const float*)d_in[12];
    const float* W1  =(const float*)d_in[13];
    const float* b1  =(const float*)d_in[14];
    const float* W2  =(const float*)d_in[15];
    const float* b2  =(const float*)d_in[16];
    const float* W3  =(const float*)d_in[17];
    const float* b3  =(const float*)d_in[18];
    float* out = (float*)d_out;

    const int attn_smem = (128*68 + 64*128) * (int)sizeof(float);  // 67584 B
    cudaFuncSetAttribute(attn2_kernel, cudaFuncAttributeMaxDynamicSharedMemorySize, attn_smem);

    transpose_whh<<<256,256>>>(Whh);
    lstm_kernel<<<375,256>>>(Xs, Wih, bihp, bhhp, lng, lnb);
    proj_kernel<<<938,256>>>(WK, nullptr, SL_, 0);   // -> g_Hk
    proj_kernel<<<94, 256>>>(WQ, tgt,     S_,  1);   // -> g_q
    attn2_kernel<<<dim3(47,NSPLIT_),256, attn_smem>>>(logt, lagb, tgt);
    final_kernel<<<12,256>>>(Xr, W1,b1, W2,b2, W3,b3, out);
}

// round 4
// speedup vs baseline: 1.7124x; 1.0623x over previous
#include <cuda_runtime.h>
#include <math.h>
#include <float.h>

#define S_    3000
#define F_    6
#define N_    128
#define L_    40
#define LMAX_ 10
#define K_    5
#define SL_   (S_*LMAX_)   // 30000
#define NTILE_ 469         // ceil(30000/64)
#define NSPLIT_ 8
#define TILES_PER_SPLIT_ 59

typedef unsigned long long u64;

// ---------------- f32x2 packed-FMA helpers (sm_100+) ------------------------
__device__ __forceinline__ u64 pk2(float lo, float hi){
    u64 r;
    asm("mov.b64 %0,{%1,%2};" : "=l"(r)
        : "r"(__float_as_uint(lo)), "r"(__float_as_uint(hi)));
    return r;
}
__device__ __forceinline__ u64 dup2(float v){ return pk2(v, v); }
__device__ __forceinline__ float2 upk2(u64 v){
    unsigned lo, hi;
    asm("mov.b64 {%0,%1},%2;" : "=r"(lo), "=r"(hi) : "l"(v));
    float2 f; f.x = __uint_as_float(lo); f.y = __uint_as_float(hi); return f;
}
__device__ __forceinline__ void fma2(u64& d, u64 a, u64 b){
    asm("fma.rn.f32x2 %0,%1,%2,%0;" : "+l"(d) : "l"(a), "l"(b));
}

// ---------------- scratch (device globals; no allocations allowed) ----------
__device__ float g_WhhT[N_*4*N_];        // [128][512] k-major transpose of Whh
__device__ float g_Hln[SL_*N_];          // [30000][128] layernormed H, t in [30,40)
__device__ float g_Hk [SL_*N_];          // l2norm(Hln @ WK^T)
__device__ float g_q  [S_*N_];           // l2norm(Hln[tgt,9] @ WQ^T)
__device__ float g_pval[S_*40];          // 8 splits x top5 per target
__device__ int   g_pidx[S_*40];

__device__ __forceinline__ float sigf(float x){ return 1.f/(1.f+__expf(-x)); }
__device__ __forceinline__ float tanhfast(float x){ return 2.f/(1.f+__expf(-2.f*x)) - 1.f; }
__device__ __forceinline__ bool better(float v,int i,float bv,int bi){
    return (v>bv) || (v==bv && i<bi);
}

// ---------------- kernel 0: transpose Whh [512][128] -> [128][512] ----------
__global__ void __launch_bounds__(256) transpose_whh(const float* __restrict__ Whh){
    int idx = blockIdx.x*256 + threadIdx.x;          // 65536 elements
    if (idx < 512*128){
        int j = idx >> 7, k = idx & 127;
        g_WhhT[k*512 + j] = Whh[idx];
    }
}

// ---------------- kernel 1: LSTM (+ fused LayerNorm for t>=30) --------------
// 8 stocks per block, 256 threads.
// GEMM phase: thread owns 4 gate cols x 4 stocks (f32x2 packed over col pairs).
// Update phase: warp w <-> stock w, thread owns 4 units.
__global__ void __launch_bounds__(256) lstm_kernel(
    const float* __restrict__ X,   const float* __restrict__ Wih,
    const float* __restrict__ bih, const float* __restrict__ bhh,
    const float* __restrict__ lng, const float* __restrict__ lnb)
{
    __shared__ float sh[8][128];      // hidden state
    __shared__ float sg[8][512];      // gates
    __shared__ float sx[8][240];      // x for 40 steps * 6 feats
    const int tid = threadIdx.x;
    const int bs0 = blockIdx.x*8;

    for (int idx=tid; idx<8*240; idx+=256)
        sx[idx/240][idx%240] = X[(bs0 + idx/240)*240 + idx%240];
    for (int idx=tid; idx<1024; idx+=256) ((float*)sh)[idx] = 0.f;

    const int j0  = (tid & 127)*4;   // gate col base (0..508)
    const int st0 = (tid >> 7)*4;    // stock group base (0 or 4)

    // pre-pack Wih col-pairs and bias
    u64 wihp[6][2];
    #pragma unroll
    for (int f=0; f<6; f++){
        wihp[f][0] = pk2(Wih[(j0+0)*6+f], Wih[(j0+1)*6+f]);
        wihp[f][1] = pk2(Wih[(j0+2)*6+f], Wih[(j0+3)*6+f]);
    }
    u64 bias2[2];
    bias2[0] = pk2(bih[j0+0]+bhh[j0+0], bih[j0+1]+bhh[j0+1]);
    bias2[1] = pk2(bih[j0+2]+bhh[j0+2], bih[j0+3]+bhh[j0+3]);

    const int su = tid>>5;             // stock for update phase (warp id)
    const int n0 = (tid&31)*4;         // unit base
    float c0=0.f,c1=0.f,c2=0.f,c3=0.f;
    const float4 g4 = *(const float4*)&lng[n0];
    const float4 b4 = *(const float4*)&lnb[n0];

    for (int t=0; t<40; t++){
        __syncthreads();
        u64 acc2[4][2];
        #pragma unroll
        for (int s=0;s<4;s++){ acc2[s][0]=bias2[0]; acc2[s][1]=bias2[1]; }
        // input contribution
        #pragma unroll
        for (int f=0;f<6;f++){
            u64 w0 = wihp[f][0], w1 = wihp[f][1];
            #pragma unroll
            for (int s=0;s<4;s++){
                u64 xd = dup2(sx[st0+s][t*6+f]);
                fma2(acc2[s][0], xd, w0);
                fma2(acc2[s][1], xd, w1);
            }
        }
        // hidden contribution: k over 128, quad-unrolled
        #pragma unroll 4
        for (int kb=0; kb<32; kb++){
            float4 w4[4];
            #pragma unroll
            for (int kk=0;kk<4;kk++)
                w4[kk] = *(const float4*)&g_WhhT[(kb*4+kk)*512 + j0];
            float4 hv[4];
            #pragma unroll
            for (int s=0;s<4;s++)
                hv[s] = *(const float4*)&sh[st0+s][kb*4];   // warp-broadcast
            const float* hvf = (const float*)hv;            // hvf[s*4+kk]
            #pragma unroll
            for (int kk=0;kk<4;kk++){
                u64 wlo = pk2(w4[kk].x, w4[kk].y);
                u64 whi = pk2(w4[kk].z, w4[kk].w);
                #pragma unroll
                for (int s=0;s<4;s++){
                    u64 hd = dup2(hvf[s*4+kk]);
                    fma2(acc2[s][0], hd, wlo);
                    fma2(acc2[s][1], hd, whi);
                }
            }
        }
        #pragma unroll
        for (int s=0;s<4;s++){
            float2 lo = upk2(acc2[s][0]);
            float2 hi = upk2(acc2[s][1]);
            float4 gv; gv.x=lo.x; gv.y=lo.y; gv.z=hi.x; gv.w=hi.y;
            *(float4*)&sg[st0+s][j0] = gv;
        }
        __syncthreads();

        float4 gi = *(const float4*)&sg[su][n0];
        float4 gf = *(const float4*)&sg[su][128+n0];
        float4 gg = *(const float4*)&sg[su][256+n0];
        float4 go = *(const float4*)&sg[su][384+n0];
        c0 = sigf(gf.x)*c0 + sigf(gi.x)*tanhfast(gg.x);
        c1 = sigf(gf.y)*c1 + sigf(gi.y)*tanhfast(gg.y);
        c2 = sigf(gf.z)*c2 + sigf(gi.z)*tanhfast(gg.z);
        c3 = sigf(gf.w)*c3 + sigf(gi.w)*tanhfast(gg.w);
        float4 h4;
        h4.x = sigf(go.x)*tanhfast(c0);
        h4.y = sigf(go.y)*tanhfast(c1);
        h4.z = sigf(go.z)*tanhfast(c2);
        h4.w = sigf(go.w)*tanhfast(c3);
        *(float4*)&sh[su][n0] = h4;

        if (t >= 30){
            float sum = h4.x+h4.y+h4.z+h4.w;
            float ssq = h4.x*h4.x+h4.y*h4.y+h4.z*h4.z+h4.w*h4.w;
            #pragma unroll
            for (int o=16;o>=1;o>>=1){
                sum += __shfl_xor_sync(0xffffffffu, sum, o);
                ssq += __shfl_xor_sync(0xffffffffu, ssq, o);
            }
            float mean = sum*(1.f/128.f);
            float var  = ssq*(1.f/128.f) - mean*mean;
            float rstd = rsqrtf(var + 1e-5f);
            float4 o4;
            o4.x = (h4.x-mean)*rstd*g4.x + b4.x;
            o4.y = (h4.y-mean)*rstd*g4.y + b4.y;
            o4.z = (h4.z-mean)*rstd*g4.z + b4.z;
            o4.w = (h4.w-mean)*rstd*g4.w + b4.w;
            *(float4*)&g_Hln[((bs0+su)*10 + (t-30))*128 + n0] = o4;
        }
    }
}

// ---------------- kernel 2: register-tiled projection + row l2norm ---------
// Block: 64 rows x 128 cols, 256 threads (16x16), thread = 4 rows x 8 cols.
// W^T staged k-major in SMEM once; f32x2 packed over row pairs.
__global__ void __launch_bounds__(256) proj2_kernel(
    const float* __restrict__ W, const int* __restrict__ gatherIdx,
    int nrows, int which)
{
    extern __shared__ float ps[];
    float* sW  = ps;              // [128][132] k-major W^T
    float* sAT = ps + 128*132;    // [128][68]  k-major A tile
    float* out = which ? g_q : g_Hk;

    const int tid = threadIdx.x;
    const int tx  = tid & 15, ty = tid >> 4;
    const int r0  = blockIdx.x*64;

    for (int idx=tid; idx<128*32; idx+=256){
        int j = idx >> 5, kq = idx & 31;
        float4 v = *(const float4*)&W[j*128 + kq*4];
        sW[(kq*4+0)*132 + j] = v.x;
        sW[(kq*4+1)*132 + j] = v.y;
        sW[(kq*4+2)*132 + j] = v.z;
        sW[(kq*4+3)*132 + j] = v.w;
    }
    for (int idx=tid; idx<64*32; idx+=256){
        int r = idx >> 5, kq = idx & 31;
        int gr = r0 + r;
        float4 v = make_float4(0.f,0.f,0.f,0.f);
        if (gr < nrows){
            int src = gatherIdx ? (gatherIdx[gr]*10 + 9) : gr;
            v = *(const float4*)&g_Hln[src*128 + kq*4];
        }
        sAT[(kq*4+0)*68 + r] = v.x;
        sAT[(kq*4+1)*68 + r] = v.y;
        sAT[(kq*4+2)*68 + r] = v.z;
        sAT[(kq*4+3)*68 + r] = v.w;
    }
    __syncthreads();

    u64 acc2[2][8];
    #pragma unroll
    for (int c=0;c<8;c++){ acc2[0][c]=0ull; acc2[1][c]=0ull; }

    const float* arow = &sAT[ty*4];
    const float* wrow = &sW[tx*8];
    #pragma unroll 4
    for (int k=0;k<128;k++){
        float4 av = *(const float4*)&arow[k*68];
        float4 w0 = *(const float4*)&wrow[k*132];
        float4 w1 = *(const float4*)&wrow[k*132 + 4];
        u64 alo = pk2(av.x, av.y);
        u64 ahi = pk2(av.z, av.w);
        const float wv[8] = {w0.x,w0.y,w0.z,w0.w,w1.x,w1.y,w1.z,w1.w};
        #pragma unroll
        for (int c=0;c<8;c++){
            u64 bd = dup2(wv[c]);
            fma2(acc2[0][c], alo, bd);
            fma2(acc2[1][c], ahi, bd);
        }
    }

    float accf[4][8];
    #pragma unroll
    for (int c=0;c<8;c++){
        float2 lo = upk2(acc2[0][c]); accf[0][c]=lo.x; accf[1][c]=lo.y;
        float2 hi = upk2(acc2[1][c]); accf[2][c]=hi.x; accf[3][c]=hi.y;
    }
    #pragma unroll
    for (int r=0;r<4;r++){
        float ss=0.f;
        #pragma unroll
        for (int c=0;c<8;c++) ss += accf[r][c]*accf[r][c];
        #pragma unroll
        for (int o=8;o>=1;o>>=1) ss += __shfl_xor_sync(0xffffffffu, ss, o);
        float inv = 1.f/fmaxf(sqrtf(ss), 1e-12f);
        int gr = r0 + ty*4 + r;
        if (gr < nrows){
            float4 o0, o1;
            o0.x=accf[r][0]*inv; o0.y=accf[r][1]*inv; o0.z=accf[r][2]*inv; o0.w=accf[r][3]*inv;
            o1.x=accf[r][4]*inv; o1.y=accf[r][5]*inv; o1.z=accf[r][6]*inv; o1.w=accf[r][7]*inv;
            *(float4*)&out[gr*128 + tx*8]     = o0;
            *(float4*)&out[gr*128 + tx*8 + 4] = o1;
        }
    }
}

// ---------------- kernel 3: register-tiled attention GEMM + fused top-5 ----
// Block: 64 targets x 64 cols per tile, 256 threads (16x16), thread = 4x4
// (f32x2 packed over row pairs). grid (47 row tiles, 8 col splits).
__global__ void __launch_bounds__(256) attn2_kernel(
    const float* __restrict__ log_temp, const float* __restrict__ lag_bias,
    const int*   __restrict__ target_idx)
{
    extern __shared__ float smem[];
    float* sAT = smem;               // [128][68]  k-major A
    float* sB  = smem + 128*68;      // [64][128]  swizzled B tile
    __shared__ float slb[10];
    __shared__ float sinvt;

    const int tid = threadIdx.x;
    const int tx  = tid & 15, ty = tid >> 4;
    const int rbase = blockIdx.x*64;

    if (tid < 10) slb[tid] = lag_bias[tid];
    if (tid == 0){
        float tp = __expf(log_temp[0]);
        tp = fminf(fmaxf(tp, 0.1f), 11.313708498984761f);
        sinvt = 1.f/tp;
    }

    for (int idx = tid; idx < 64*32; idx += 256){
        int row = idx >> 5, kq = idx & 31;
        int gr = rbase + row;
        float4 v = make_float4(0.f,0.f,0.f,0.f);
        if (gr < S_) v = *(const float4*)&g_q[gr*128 + kq*4];
        sAT[(kq*4+0)*68 + row] = v.x;
        sAT[(kq*4+1)*68 + row] = v.y;
        sAT[(kq*4+2)*68 + row] = v.z;
        sAT[(kq*4+3)*68 + row] = v.w;
    }

    int myst[4];
    #pragma unroll
    for (int i=0;i<4;i++){
        int gr = rbase + ty*4 + i;
        myst[i] = (gr < S_) ? target_idx[gr] : -1;
    }

    float tv[4][5]; int ti[4][5];
    #pragma unroll
    for (int r=0;r<4;r++)
        #pragma unroll
        for (int p=0;p<5;p++){ tv[r][p] = -FLT_MAX; ti[r][p] = 0x7fffffff; }

    __syncthreads();
    const float invt = sinvt;
    const int swz = tx & 7;
    const int tstart = blockIdx.y*TILES_PER_SPLIT_;
    const int tend   = min(tstart+TILES_PER_SPLIT_, NTILE_);

    for (int tile = tstart; tile < tend; tile++){
        const int c0 = tile*64;
        __syncthreads();
        for (int idx = tid; idx < 64*32; idx += 256){
            int col = idx >> 5, kq = idx & 31;
            int gc = c0 + col;
            float4 v = make_float4(0.f,0.f,0.f,0.f);
            if (gc < SL_) v = *(const float4*)&g_Hk[gc*128 + kq*4];
            int ks = kq ^ ((col>>2)&7);
            *(float4*)&sB[col*128 + ks*4] = v;
        }
        __syncthreads();

        u64 acc2[2][4];
        #pragma unroll
        for (int c=0;c<4;c++){ acc2[0][c]=0ull; acc2[1][c]=0ull; }

        const float* arow  = &sAT[ty*4];
        const float* bbase = &sB[(tx*4)*128];

        #pragma unroll 4
        for (int kb = 0; kb < 32; kb++){
            float4 Af[4];
            Af[0] = *(const float4*)&arow[(kb*4+0)*68];
            Af[1] = *(const float4*)&arow[(kb*4+1)*68];
            Af[2] = *(const float4*)&arow[(kb*4+2)*68];
            Af[3] = *(const float4*)&arow[(kb*4+3)*68];
            const int ks = (kb ^ swz)*4;
            float4 Bf[4];
            Bf[0] = *(const float4*)&bbase[0*128 + ks];
            Bf[1] = *(const float4*)&bbase[1*128 + ks];
            Bf[2] = *(const float4*)&bbase[2*128 + ks];
            Bf[3] = *(const float4*)&bbase[3*128 + ks];
            const float* av = (const float*)Af;   // av[k*4 + r]
            const float* bv = (const float*)Bf;   // bv[c*4 + k]
            #pragma unroll
            for (int k=0;k<4;k++){
                u64 alo = pk2(av[k*4+0], av[k*4+1]);
                u64 ahi = pk2(av[k*4+2], av[k*4+3]);
                #pragma unroll
                for (int c=0;c<4;c++){
                    u64 bd = dup2(bv[c*4+k]);
                    fma2(acc2[0][c], alo, bd);
                    fma2(acc2[1][c], ahi, bd);
                }
            }
        }

        float acc[4][4];
        #pragma unroll
        for (int c=0;c<4;c++){
            float2 lo = upk2(acc2[0][c]); acc[0][c]=lo.x; acc[1][c]=lo.y;
            float2 hi = upk2(acc2[1][c]); acc[2][c]=hi.x; acc[3][c]=hi.y;
        }

        // scores + top-5 update
        #pragma unroll
        for (int c=0;c<4;c++){
            int gc = c0 + tx*4 + c;
            int s  = gc/10;
            int l  = gc - s*10;
            bool colok = (gc < SL_);
            float lb = slb[l];
            #pragma unroll
            for (int r=0;r<4;r++){
                if (!colok || s == myst[r]) continue;
                float sc = acc[r][c]*invt + lb;
                if (better(sc, gc, tv[r][4], ti[r][4])){
                    tv[r][4]=sc; ti[r][4]=gc;
                    #pragma unroll
                    for (int p=4;p>0;p--){
                        if (better(tv[r][p],ti[r][p],tv[r][p-1],ti[r][p-1])){
                            float tvv=tv[r][p]; tv[r][p]=tv[r][p-1]; tv[r][p-1]=tvv;
                            int   tii=ti[r][p]; ti[r][p]=ti[r][p-1]; ti[r][p-1]=tii;
                        }
                    }
                }
            }
        }
    }

    // Merge 16 partial top-5 lists per row (alias smem over GEMM tiles)
    __syncthreads();
    float* mv = smem;                         // [64][16][5] floats (20KB)
    int*   mi = (int*)(smem + 64*16*5);       // [64][16][5] ints   (20KB)
    #pragma unroll
    for (int r=0;r<4;r++){
        int row = ty*4+r;
        #pragma unroll
        for (int p=0;p<5;p++){
            mv[(row*16+tx)*5+p] = tv[r][p];
            mi[(row*16+tx)*5+p] = ti[r][p];
        }
    }
    __syncthreads();
    if (tid < 64){
        int gr = rbase + tid;
        if (gr < S_){
            float* cv = &mv[tid*80];
            int*   ci = &mi[tid*80];
            for (int kk=0;kk<5;kk++){
                float bv=-FLT_MAX; int bi=0x7fffffff; int bp=0;
                for (int m=0;m<80;m++){
                    if (better(cv[m],ci[m],bv,bi)){ bv=cv[m]; bi=ci[m]; bp=m; }
                }
                g_pval[gr*40 + blockIdx.y*5 + kk]=bv;
                g_pidx[gr*40 + blockIdx.y*5 + kk]=bi;
                cv[bp]=-FLT_MAX; ci[bp]=0x7fffffff;
            }
        }
    }
}

// ---------------- kernel 4: merge + softmax + gather + MLP -----------------
__global__ void __launch_bounds__(256) final_kernel(
    const float* __restrict__ Xraw,
    const float* __restrict__ W1, const float* __restrict__ b1,
    const float* __restrict__ W2, const float* __restrict__ b2,
    const float* __restrict__ W3, const float* __restrict__ b3,
    float* __restrict__ out)
{
    int t = blockIdx.x*256 + threadIdx.x;
    if (t >= S_) return;
    float cv[40]; int ci[40];
    #pragma unroll
    for (int m=0;m<40;m++){ cv[m]=g_pval[t*40+m]; ci[m]=g_pidx[t*40+m]; }
    float v5[5]; int i5[5];
    #pragma unroll
    for (int kk=0;kk<5;kk++){
        float bv=-FLT_MAX; int bi=0x7fffffff; int bp=0;
        #pragma unroll
        for (int m=0;m<40;m++)
            if (better(cv[m],ci[m],bv,bi)){ bv=cv[m]; bi=ci[m]; bp=m; }
        v5[kk]=bv; i5[kk]=bi;
        cv[bp]=-FLT_MAX; ci[bp]=0x7fffffff;
    }
    float w[5]; float den=0.f;
    #pragma unroll
    for (int kk=0;kk<5;kk++){ w[kk]=__expf(v5[kk]-v5[0]); den+=w[kk]; }
    float invden = 1.f/den;
    float feat[12];
    float zagg[6] = {0,0,0,0,0,0};
    #pragma unroll
    for (int kk=0;kk<5;kk++){
        int idx = i5[kk];
        int leader = idx/10;
        int lag    = idx - leader*10;
        int pos    = 29 + lag;
        const float* zp = &Xraw[(leader*40 + pos)*6];
        float ww = w[kk]*invden;
        #pragma unroll
        for (int f=0;f<6;f++){
            float zf = zp[f];
            zagg[f] += ww*zf;
            if (kk==0) feat[6+f]=zf;
        }
    }
    #pragma unroll
    for (int f=0;f<6;f++) feat[f]=zagg[f];

    float h1[64];
    #pragma unroll
    for (int j=0;j<64;j++){
        float a = b1[j];
        #pragma unroll
        for (int f=0;f<12;f++) a += W1[j*12+f]*feat[f];
        h1[j] = fmaxf(a,0.f);
    }
    float h2[32];
    #pragma unroll
    for (int j=0;j<32;j++){
        float a = b2[j];
        #pragma unroll
        for (int f=0;f<64;f++) a += W2[j*64+f]*h1[f];
        h2[j] = fmaxf(a,0.f);
    }
    float a = b3[0];
    #pragma unroll
    for (int j=0;j<32;j++) a += W3[j]*h2[j];
    out[t] = a;
}

// ---------------- launch ----------------------------------------------------
extern "C" void kernel_launch(void* const* d_in, const int* in_sizes, int n_in,
                              void* d_out, int out_size)
{
    const float* Xs  =(const float*)d_in[0];
    const float* Xr  =(const float*)d_in[1];
    const int*   tgt =(const int*)  d_in[2];
    const float* Wih =(const float*)d_in[3];
    const float* Whh =(const float*)d_in[4];
    const float* bihp=(const float*)d_in[5];
    const float* bhhp=(const float*)d_in[6];
    const float* lng =(const float*)d_in[7];
    const float* lnb =(const float*)d_in[8];
    const float* WQ  =(const float*)d_in[9];
    const float* WK  =(const float*)d_in[10];
    const float* logt=(const float*)d_in[11];
    const float* lagb=(const float*)d_in[12];
    const float* W1  =(const float*)d_in[13];
    const float* b1  =(const float*)d_in[14];
    const float* W2  =(const float*)d_in[15];
    const float* b2  =(const float*)d_in[16];
    const float* W3  =(const float*)d_in[17];
    const float* b3  =(const float*)d_in[18];
    float* out = (float*)d_out;

    const int attn_smem = (128*68 + 64*128) * (int)sizeof(float);   // 67584 B
    const int proj_smem = (128*132 + 128*68) * (int)sizeof(float);  // 102400 B
    cudaFuncSetAttribute(attn2_kernel, cudaFuncAttributeMaxDynamicSharedMemorySize, attn_smem);
    cudaFuncSetAttribute(proj2_kernel, cudaFuncAttributeMaxDynamicSharedMemorySize, proj_smem);

    transpose_whh<<<256,256>>>(Whh);
    lstm_kernel<<<375,256>>>(Xs, Wih, bihp, bhhp, lng, lnb);
    proj2_kernel<<<469,256, proj_smem>>>(WK, nullptr, SL_, 0);   // -> g_Hk
    proj2_kernel<<<47, 256, proj_smem>>>(WQ, tgt,     S_,  1);   // -> g_q
    attn2_kernel<<<dim3(47,NSPLIT_),256, attn_smem>>>(logt, lagb, tgt);
    final_kernel<<<12,256>>>(Xr, W1,b1, W2,b2, W3,b3, out);
}

// round 5
// speedup vs baseline: 2.4302x; 1.4192x over previous
#include <cuda_runtime.h>
#include <math.h>
#include <float.h>

#define S_    3000
#define F_    6
#define N_    128
#define L_    40
#define LMAX_ 10
#define K_    5
#define SL_   (S_*LMAX_)   // 30000
#define NTILE_ 469         // ceil(30000/64)
#define NSPLIT_ 6
#define TILES_PER_SPLIT_ 79
#define NS5_  (NSPLIT_*K_) // 30
#define NSTK_ 12           // stocks per LSTM block
#define NBLK_ 250          // 250*12 = 3000

typedef unsigned long long u64;

// ---------------- f32x2 packed-FMA helpers (sm_100+) ------------------------
__device__ __forceinline__ u64 pk2(float lo, float hi){
    u64 r;
    asm("mov.b64 %0,{%1,%2};" : "=l"(r)
        : "r"(__float_as_uint(lo)), "r"(__float_as_uint(hi)));
    return r;
}
__device__ __forceinline__ u64 dup2(float v){ return pk2(v, v); }
__device__ __forceinline__ float2 upk2(u64 v){
    unsigned lo, hi;
    asm("mov.b64 {%0,%1},%2;" : "=r"(lo), "=r"(hi) : "l"(v));
    float2 f; f.x = __uint_as_float(lo); f.y = __uint_as_float(hi); return f;
}
__device__ __forceinline__ void fma2(u64& d, u64 a, u64 b){
    asm("fma.rn.f32x2 %0,%1,%2,%0;" : "+l"(d) : "l"(a), "l"(b));
}

// ---------------- cp.async helpers ------------------------------------------
__device__ __forceinline__ void cp16(float* dst, const float* src, bool valid){
    unsigned d = (unsigned)__cvta_generic_to_shared(dst);
    int sz = valid ? 16 : 0;
    asm volatile("cp.async.cg.shared.global [%0], [%1], 16, %2;"
                 :: "r"(d), "l"(src), "r"(sz));
}
__device__ __forceinline__ void cp_commit(){
    asm volatile("cp.async.commit_group;" ::: "memory");
}

// ---------------- scratch (device globals; no allocations allowed) ----------
__device__ u64   g_Whh2[128*256];        // [k][256] u64 = packed col-pairs of Whh^T
__device__ float g_Hln[SL_*N_];          // [30000][128] layernormed H, t in [30,40)
__device__ float g_Hk [SL_*N_];          // l2norm(Hln @ WK^T)
__device__ float g_q  [S_*N_];           // l2norm(Hln[tgt,9] @ WQ^T)
__device__ float g_pval[S_*40];          // 6 splits x top5 per target
__device__ int   g_pidx[S_*40];

__device__ __forceinline__ float sigf(float x){ return 1.f/(1.f+__expf(-x)); }
__device__ __forceinline__ float tanhfast(float x){ return 2.f/(1.f+__expf(-2.f*x)) - 1.f; }
__device__ __forceinline__ bool better(float v,int i,float bv,int bi){
    return (v>bv) || (v==bv && i<bi);
}

// ---------------- kernel 0: pack Whh -> g_Whh2 [k][j] = (Whh[2j][k],Whh[2j+1][k])
__global__ void __launch_bounds__(256) pack_whh(const float* __restrict__ Whh){
    int idx = blockIdx.x*256 + threadIdx.x;          // 32768 elements
    if (idx < 128*256){
        int k = idx >> 8, j = idx & 255;
        g_Whh2[idx] = pk2(Whh[(2*j)*128 + k], Whh[(2*j+1)*128 + k]);
    }
}

// ---------------- kernel 1: LSTM (+ fused LayerNorm for t>=30) --------------
// 12 stocks per block, 256 threads, 250 blocks.
// GEMM phase: thread owns 2 gate cols (j0=2*tid) for ALL 12 stocks
//   (acc packed over stock pairs). Whh read ONCE per block per step.
// Update phase: threads 0..191: su = tid>>4, 8 units n0=(tid&15)*8.
__global__ void __launch_bounds__(256) lstm_kernel(
    const float* __restrict__ X,   const float* __restrict__ Wih,
    const float* __restrict__ bih, const float* __restrict__ bhh,
    const float* __restrict__ lng, const float* __restrict__ lnb)
{
    __shared__ float shT[128*14];        // h transposed: [k][stock], pad 14
    __shared__ float sg[NSTK_][516];     // gates [stock][512+pad]
    __shared__ u64   sx2[240*6];         // x packed stock-pairs: [t*6+f][pair]
    const int tid = threadIdx.x;
    const int bs0 = blockIdx.x*NSTK_;

    // pack x into stock-pair u64s
    for (int idx = tid; idx < 240*6; idx += 256){
        int tf = idx/6, p = idx - (idx/6)*6;
        sx2[tf*6 + p] = pk2(X[(bs0 + 2*p)*240 + tf], X[(bs0 + 2*p+1)*240 + tf]);
    }
    for (int idx = tid; idx < 128*14; idx += 256) shT[idx] = 0.f;

    const int j0 = tid*2;                // gate cols j0, j0+1
    // dup'd Wih and bias (loop-invariant)
    u64 wih_d[2][6];
    #pragma unroll
    for (int c=0;c<2;c++)
        #pragma unroll
        for (int f=0;f<6;f++) wih_d[c][f] = dup2(Wih[(j0+c)*6 + f]);
    u64 bias_d[2];
    bias_d[0] = dup2(bih[j0]   + bhh[j0]);
    bias_d[1] = dup2(bih[j0+1] + bhh[j0+1]);

    // update-phase mapping
    const int su = tid >> 4;             // 0..15 (active if <12)
    const int n0 = (tid & 15)*8;         // unit base, 8 units
    float4 cA = make_float4(0.f,0.f,0.f,0.f);
    float4 cB = make_float4(0.f,0.f,0.f,0.f);
    float4 gA4, gB4, bA4, bB4;
    if (su < NSTK_){
        gA4 = *(const float4*)&lng[n0];   gB4 = *(const float4*)&lng[n0+4];
        bA4 = *(const float4*)&lnb[n0];   bB4 = *(const float4*)&lnb[n0+4];
    }

    for (int t=0; t<40; t++){
        __syncthreads();
        // ---- gate GEMM: acc[pair][col], lanes = stocks (2p, 2p+1)
        u64 acc[6][2];
        #pragma unroll
        for (int p=0;p<6;p++){ acc[p][0]=bias_d[0]; acc[p][1]=bias_d[1]; }
        #pragma unroll
        for (int f=0;f<6;f++){
            u64 w0 = wih_d[0][f], w1 = wih_d[1][f];
            #pragma unroll
            for (int p=0;p<6;p++){
                u64 xp = sx2[(t*6+f)*6 + p];
                fma2(acc[p][0], xp, w0);
                fma2(acc[p][1], xp, w1);
            }
        }
        #pragma unroll 2
        for (int k4=0; k4<32; k4++){
            u64 w2[4];
            #pragma unroll
            for (int kk=0;kk<4;kk++)
                w2[kk] = g_Whh2[(k4*4+kk)*256 + tid];
            #pragma unroll
            for (int kk=0;kk<4;kk++){
                int k = k4*4+kk;
                float2 wf = upk2(w2[kk]);
                u64 wd0 = dup2(wf.x), wd1 = dup2(wf.y);
                #pragma unroll
                for (int p=0;p<6;p++){
                    u64 hp = *(const u64*)&shT[k*14 + 2*p];
                    fma2(acc[p][0], hp, wd0);
                    fma2(acc[p][1], hp, wd1);
                }
            }
        }
        #pragma unroll
        for (int p=0;p<6;p++){
            float2 a0 = upk2(acc[p][0]);   // col j0: stocks 2p, 2p+1
            float2 a1 = upk2(acc[p][1]);   // col j0+1
            sg[2*p  ][j0  ] = a0.x;
            sg[2*p+1][j0  ] = a0.y;
            sg[2*p  ][j0+1] = a1.x;
            sg[2*p+1][j0+1] = a1.y;
        }
        __syncthreads();

        // ---- cell update (threads with su < 12)
        if (su < NSTK_){
            float4 giA = *(const float4*)&sg[su][n0];
            float4 giB = *(const float4*)&sg[su][n0+4];
            float4 gfA = *(const float4*)&sg[su][128+n0];
            float4 gfB = *(const float4*)&sg[su][128+n0+4];
            float4 ggA = *(const float4*)&sg[su][256+n0];
            float4 ggB = *(const float4*)&sg[su][256+n0+4];
            float4 goA = *(const float4*)&sg[su][384+n0];
            float4 goB = *(const float4*)&sg[su][384+n0+4];

            cA.x = sigf(gfA.x)*cA.x + sigf(giA.x)*tanhfast(ggA.x);
            cA.y = sigf(gfA.y)*cA.y + sigf(giA.y)*tanhfast(ggA.y);
            cA.z = sigf(gfA.z)*cA.z + sigf(giA.z)*tanhfast(ggA.z);
            cA.w = sigf(gfA.w)*cA.w + sigf(giA.w)*tanhfast(ggA.w);
            cB.x = sigf(gfB.x)*cB.x + sigf(giB.x)*tanhfast(ggB.x);
            cB.y = sigf(gfB.y)*cB.y + sigf(giB.y)*tanhfast(ggB.y);
            cB.z = sigf(gfB.z)*cB.z + sigf(giB.z)*tanhfast(ggB.z);
            cB.w = sigf(gfB.w)*cB.w + sigf(giB.w)*tanhfast(ggB.w);

            float hA0 = sigf(goA.x)*tanhfast(cA.x);
            float hA1 = sigf(goA.y)*tanhfast(cA.y);
            float hA2 = sigf(goA.z)*tanhfast(cA.z);
            float hA3 = sigf(goA.w)*tanhfast(cA.w);
            float hB0 = sigf(goB.x)*tanhfast(cB.x);
            float hB1 = sigf(goB.y)*tanhfast(cB.y);
            float hB2 = sigf(goB.z)*tanhfast(cB.z);
            float hB3 = sigf(goB.w)*tanhfast(cB.w);

            // write transposed h for next step's GEMM
            shT[(n0+0)*14 + su] = hA0;
            shT[(n0+1)*14 + su] = hA1;
            shT[(n0+2)*14 + su] = hA2;
            shT[(n0+3)*14 + su] = hA3;
            shT[(n0+4)*14 + su] = hB0;
            shT[(n0+5)*14 + su] = hB1;
            shT[(n0+6)*14 + su] = hB2;
            shT[(n0+7)*14 + su] = hB3;

            if (t >= 30){
                float sum = hA0+hA1+hA2+hA3+hB0+hB1+hB2+hB3;
                float ssq = hA0*hA0+hA1*hA1+hA2*hA2+hA3*hA3
                          + hB0*hB0+hB1*hB1+hB2*hB2+hB3*hB3;
                #pragma unroll
                for (int o=8;o>=1;o>>=1){
                    sum += __shfl_xor_sync(0xffffffffu, sum, o, 16);
                    ssq += __shfl_xor_sync(0xffffffffu, ssq, o, 16);
                }
                float mean = sum*(1.f/128.f);
                float var  = ssq*(1.f/128.f) - mean*mean;
                float rstd = rsqrtf(var + 1e-5f);
                float4 oA, oB;
                oA.x = (hA0-mean)*rstd*gA4.x + bA4.x;
                oA.y = (hA1-mean)*rstd*gA4.y + bA4.y;
                oA.z = (hA2-mean)*rstd*gA4.z + bA4.z;
                oA.w = (hA3-mean)*rstd*gA4.w + bA4.w;
                oB.x = (hB0-mean)*rstd*gB4.x + bB4.x;
                oB.y = (hB1-mean)*rstd*gB4.y + bB4.y;
                oB.z = (hB2-mean)*rstd*gB4.z + bB4.z;
                oB.w = (hB3-mean)*rstd*gB4.w + bB4.w;
                float* dst = &g_Hln[((bs0+su)*10 + (t-30))*128 + n0];
                *(float4*)dst       = oA;
                *(float4*)(dst + 4) = oB;
            }
        }
    }
}

// ---------------- kernel 2: register-tiled projection + row l2norm ---------
__global__ void __launch_bounds__(256) proj2_kernel(
    const float* __restrict__ W, const int* __restrict__ gatherIdx,
    int nrows, int which)
{
    extern __shared__ float ps[];
    float* sW  = ps;              // [128][132] k-major W^T
    float* sAT = ps + 128*132;    // [128][68]  k-major A tile
    float* out = which ? g_q : g_Hk;

    const int tid = threadIdx.x;
    const int tx  = tid & 15, ty = tid >> 4;
    const int r0  = blockIdx.x*64;

    for (int idx=tid; idx<128*32; idx+=256){
        int j = idx >> 5, kq = idx & 31;
        float4 v = *(const float4*)&W[j*128 + kq*4];
        sW[(kq*4+0)*132 + j] = v.x;
        sW[(kq*4+1)*132 + j] = v.y;
        sW[(kq*4+2)*132 + j] = v.z;
        sW[(kq*4+3)*132 + j] = v.w;
    }
    for (int idx=tid; idx<64*32; idx+=256){
        int r = idx >> 5, kq = idx & 31;
        int gr = r0 + r;
        float4 v = make_float4(0.f,0.f,0.f,0.f);
        if (gr < nrows){
            int src = gatherIdx ? (gatherIdx[gr]*10 + 9) : gr;
            v = *(const float4*)&g_Hln[src*128 + kq*4];
        }
        sAT[(kq*4+0)*68 + r] = v.x;
        sAT[(kq*4+1)*68 + r] = v.y;
        sAT[(kq*4+2)*68 + r] = v.z;
        sAT[(kq*4+3)*68 + r] = v.w;
    }
    __syncthreads();

    u64 acc2[2][8];
    #pragma unroll
    for (int c=0;c<8;c++){ acc2[0][c]=0ull; acc2[1][c]=0ull; }

    const float* arow = &sAT[ty*4];
    const float* wrow = &sW[tx*8];
    #pragma unroll 4
    for (int k=0;k<128;k++){
        float4 av = *(const float4*)&arow[k*68];
        float4 w0 = *(const float4*)&wrow[k*132];
        float4 w1 = *(const float4*)&wrow[k*132 + 4];
        u64 alo = pk2(av.x, av.y);
        u64 ahi = pk2(av.z, av.w);
        const float wv[8] = {w0.x,w0.y,w0.z,w0.w,w1.x,w1.y,w1.z,w1.w};
        #pragma unroll
        for (int c=0;c<8;c++){
            u64 bd = dup2(wv[c]);
            fma2(acc2[0][c], alo, bd);
            fma2(acc2[1][c], ahi, bd);
        }
    }

    float accf[4][8];
    #pragma unroll
    for (int c=0;c<8;c++){
        float2 lo = upk2(acc2[0][c]); accf[0][c]=lo.x; accf[1][c]=lo.y;
        float2 hi = upk2(acc2[1][c]); accf[2][c]=hi.x; accf[3][c]=hi.y;
    }
    #pragma unroll
    for (int r=0;r<4;r++){
        float ss=0.f;
        #pragma unroll
        for (int c=0;c<8;c++) ss += accf[r][c]*accf[r][c];
        #pragma unroll
        for (int o=8;o>=1;o>>=1) ss += __shfl_xor_sync(0xffffffffu, ss, o);
        float inv = 1.f/fmaxf(sqrtf(ss), 1e-12f);
        int gr = r0 + ty*4 + r;
        if (gr < nrows){
            float4 o0, o1;
            o0.x=accf[r][0]*inv; o0.y=accf[r][1]*inv; o0.z=accf[r][2]*inv; o0.w=accf[r][3]*inv;
            o1.x=accf[r][4]*inv; o1.y=accf[r][5]*inv; o1.z=accf[r][6]*inv; o1.w=accf[r][7]*inv;
            *(float4*)&out[gr*128 + tx*8]     = o0;
            *(float4*)&out[gr*128 + tx*8 + 4] = o1;
        }
    }
}

// ---------------- kernel 3: attention GEMM + fused top-5, cp.async 2-stage --
__global__ void __launch_bounds__(256) attn2_kernel(
    const float* __restrict__ log_temp, const float* __restrict__ lag_bias,
    const int*   __restrict__ target_idx)
{
    extern __shared__ float smem[];
    float* sAT = smem;                   // [128][68]  k-major A
    float* sB0 = smem + 128*68;          // [64][128]  swizzled B buf 0
    float* sB1 = sB0 + 64*128;           // [64][128]  swizzled B buf 1
    __shared__ float slb[10];
    __shared__ float sinvt;

    const int tid = threadIdx.x;
    const int tx  = tid & 15, ty = tid >> 4;
    const int rbase = blockIdx.x*64;

    if (tid < 10) slb[tid] = lag_bias[tid];
    if (tid == 0){
        float tp = __expf(log_temp[0]);
        tp = fminf(fmaxf(tp, 0.1f), 11.313708498984761f);
        sinvt = 1.f/tp;
    }

    for (int idx = tid; idx < 64*32; idx += 256){
        int row = idx >> 5, kq = idx & 31;
        int gr = rbase + row;
        float4 v = make_float4(0.f,0.f,0.f,0.f);
        if (gr < S_) v = *(const float4*)&g_q[gr*128 + kq*4];
        sAT[(kq*4+0)*68 + row] = v.x;
        sAT[(kq*4+1)*68 + row] = v.y;
        sAT[(kq*4+2)*68 + row] = v.z;
        sAT[(kq*4+3)*68 + row] = v.w;
    }

    int myst[4];
    #pragma unroll
    for (int i=0;i<4;i++){
        int gr = rbase + ty*4 + i;
        myst[i] = (gr < S_) ? target_idx[gr] : -1;
    }

    float tv[4][5]; int ti[4][5];
    #pragma unroll
    for (int r=0;r<4;r++)
        #pragma unroll
        for (int p=0;p<5;p++){ tv[r][p] = -FLT_MAX; ti[r][p] = 0x7fffffff; }

    const int tstart = blockIdx.y*TILES_PER_SPLIT_;
    const int tend   = min(tstart+TILES_PER_SPLIT_, NTILE_);
    const int nt     = tend - tstart;
    const int swz    = tx & 7;

    // async B tile loader
    auto load_tile = [&](float* sB, int tile){
        const int c0 = tile*64;
        for (int idx = tid; idx < 64*32; idx += 256){
            int col = idx >> 5, kq = idx & 31;
            int gc = c0 + col;
            bool v = (gc < SL_);
            const float* src = &g_Hk[(v ? gc : 0)*128 + kq*4];
            int ks = kq ^ ((col>>2)&7);
            cp16(&sB[col*128 + ks*4], src, v);
        }
        cp_commit();
    };

    load_tile(sB0, tstart);
    if (nt > 1) load_tile(sB1, tstart+1);

    const float invt_pre = 0.f; (void)invt_pre;

    for (int i = 0; i < nt; i++){
        float* cur = (i & 1) ? sB1 : sB0;
        const int c0 = (tstart + i)*64;
        if (i+1 < nt) asm volatile("cp.async.wait_group 1;" ::: "memory");
        else          asm volatile("cp.async.wait_group 0;" ::: "memory");
        __syncthreads();

        u64 acc2[2][4];
        #pragma unroll
        for (int c=0;c<4;c++){ acc2[0][c]=0ull; acc2[1][c]=0ull; }

        const float* arow  = &sAT[ty*4];
        const float* bbase = &cur[(tx*4)*128];

        #pragma unroll 4
        for (int kb = 0; kb < 32; kb++){
            float4 Af[4];
            Af[0] = *(const float4*)&arow[(kb*4+0)*68];
            Af[1] = *(const float4*)&arow[(kb*4+1)*68];
            Af[2] = *(const float4*)&arow[(kb*4+2)*68];
            Af[3] = *(const float4*)&arow[(kb*4+3)*68];
            const int ks = (kb ^ swz)*4;
            float4 Bf[4];
            Bf[0] = *(const float4*)&bbase[0*128 + ks];
            Bf[1] = *(const float4*)&bbase[1*128 + ks];
            Bf[2] = *(const float4*)&bbase[2*128 + ks];
            Bf[3] = *(const float4*)&bbase[3*128 + ks];
            const float* av = (const float*)Af;   // av[k*4 + r]
            const float* bv = (const float*)Bf;   // bv[c*4 + k]
            #pragma unroll
            for (int k=0;k<4;k++){
                u64 alo = pk2(av[k*4+0], av[k*4+1]);
                u64 ahi = pk2(av[k*4+2], av[k*4+3]);
                #pragma unroll
                for (int c=0;c<4;c++){
                    u64 bd = dup2(bv[c*4+k]);
                    fma2(acc2[0][c], alo, bd);
                    fma2(acc2[1][c], ahi, bd);
                }
            }
        }

        float acc[4][4];
        #pragma unroll
        for (int c=0;c<4;c++){
            float2 lo = upk2(acc2[0][c]); acc[0][c]=lo.x; acc[1][c]=lo.y;
            float2 hi = upk2(acc2[1][c]); acc[2][c]=hi.x; acc[3][c]=hi.y;
        }

        const float invt = sinvt;
        #pragma unroll
        for (int c=0;c<4;c++){
            int gc = c0 + tx*4 + c;
            int s  = gc/10;
            int l  = gc - s*10;
            bool colok = (gc < SL_);
            float lb = slb[l];
            #pragma unroll
            for (int r=0;r<4;r++){
                if (!colok || s == myst[r]) continue;
                float sc = acc[r][c]*invt + lb;
                if (better(sc, gc, tv[r][4], ti[r][4])){
                    tv[r][4]=sc; ti[r][4]=gc;
                    #pragma unroll
                    for (int p=4;p>0;p--){
                        if (better(tv[r][p],ti[r][p],tv[r][p-1],ti[r][p-1])){
                            float tvv=tv[r][p]; tv[r][p]=tv[r][p-1]; tv[r][p-1]=tvv;
                            int   tii=ti[r][p]; ti[r][p]=ti[r][p-1]; ti[r][p-1]=tii;
                        }
                    }
                }
            }
        }
        __syncthreads();
        if (i+2 < nt) load_tile(cur, tstart+i+2);
    }

    // Merge 16 partial top-5 lists per row (alias smem)
    __syncthreads();
    float* mv = smem;                         // [64][16][5] floats (20KB)
    int*   mi = (int*)(smem + 64*16*5);       // [64][16][5] ints   (20KB)
    #pragma unroll
    for (int r=0;r<4;r++){
        int row = ty*4+r;
        #pragma unroll
        for (int p=0;p<5;p++){
            mv[(row*16+tx)*5+p] = tv[r][p];
            mi[(row*16+tx)*5+p] = ti[r][p];
        }
    }
    __syncthreads();
    if (tid < 64){
        int gr = rbase + tid;
        if (gr < S_){
            float* cv = &mv[tid*80];
            int*   ci = &mi[tid*80];
            for (int kk=0;kk<5;kk++){
                float bv=-FLT_MAX; int bi=0x7fffffff; int bp=0;
                for (int m=0;m<80;m++){
                    if (better(cv[m],ci[m],bv,bi)){ bv=cv[m]; bi=ci[m]; bp=m; }
                }
                g_pval[gr*40 + blockIdx.y*5 + kk]=bv;
                g_pidx[gr*40 + blockIdx.y*5 + kk]=bi;
                cv[bp]=-FLT_MAX; ci[bp]=0x7fffffff;
            }
        }
    }
}

// ---------------- kernel 4: merge + softmax + gather + MLP -----------------
__global__ void __launch_bounds__(256) final_kernel(
    const float* __restrict__ Xraw,
    const float* __restrict__ W1, const float* __restrict__ b1,
    const float* __restrict__ W2, const float* __restrict__ b2,
    const float* __restrict__ W3, const float* __restrict__ b3,
    float* __restrict__ out)
{
    int t = blockIdx.x*256 + threadIdx.x;
    if (t >= S_) return;
    float cv[NS5_]; int ci[NS5_];
    #pragma unroll
    for (int m=0;m<NS5_;m++){ cv[m]=g_pval[t*40+m]; ci[m]=g_pidx[t*40+m]; }
    float v5[5]; int i5[5];
    #pragma unroll
    for (int kk=0;kk<5;kk++){
        float bv=-FLT_MAX; int bi=0x7fffffff; int bp=0;
        #pragma unroll
        for (int m=0;m<NS5_;m++)
            if (better(cv[m],ci[m],bv,bi)){ bv=cv[m]; bi=ci[m]; bp=m; }
        v5[kk]=bv; i5[kk]=bi;
        cv[bp]=-FLT_MAX; ci[bp]=0x7fffffff;
    }
    float w[5]; float den=0.f;
    #pragma unroll
    for (int kk=0;kk<5;kk++){ w[kk]=__expf(v5[kk]-v5[0]); den+=w[kk]; }
    float invden = 1.f/den;
    float feat[12];
    float zagg[6] = {0,0,0,0,0,0};
    #pragma unroll
    for (int kk=0;kk<5;kk++){
        int idx = i5[kk];
        int leader = idx/10;
        int lag    = idx - leader*10;
        int pos    = 29 + lag;
        const float* zp = &Xraw[(leader*40 + pos)*6];
        float ww = w[kk]*invden;
        #pragma unroll
        for (int f=0;f<6;f++){
            float zf = zp[f];
            zagg[f] += ww*zf;
            if (kk==0) feat[6+f]=zf;
        }
    }
    #pragma unroll
    for (int f=0;f<6;f++) feat[f]=zagg[f];

    float h1[64];
    #pragma unroll
    for (int j=0;j<64;j++){
        float a = b1[j];
        #pragma unroll
        for (int f=0;f<12;f++) a += W1[j*12+f]*feat[f];
        h1[j] = fmaxf(a,0.f);
    }
    float h2[32];
    #pragma unroll
    for (int j=0;j<32;j++){
        float a = b2[j];
        #pragma unroll
        for (int f=0;f<64;f++) a += W2[j*64+f]*h1[f];
        h2[j] = fmaxf(a,0.f);
    }
    float a = b3[0];
    #pragma unroll
    for (int j=0;j<32;j++) a += W3[j]*h2[j];
    out[t] = a;
}

// ---------------- launch ----------------------------------------------------
extern "C" void kernel_launch(void* const* d_in, const int* in_sizes, int n_in,
                              void* d_out, int out_size)
{
    const float* Xs  =(const float*)d_in[0];
    const float* Xr  =(const float*)d_in[1];
    const int*   tgt =(const int*)  d_in[2];
    const float* Wih =(const float*)d_in[3];
    const float* Whh =(const float*)d_in[4];
    const float* bihp=(const float*)d_in[5];
    const float* bhhp=(const float*)d_in[6];
    const float* lng =(const float*)d_in[7];
    const float* lnb =(const float*)d_in[8];
    const float* WQ  =(const float*)d_in[9];
    const float* WK  =(const float*)d_in[10];
    const float* logt=(const float*)d_in[11];
    const float* lagb=(const float*)d_in[12];
    const float* W1  =(const float*)d_in[13];
    const float* b1  =(const float*)d_in[14];
    const float* W2  =(const float*)d_in[15];
    const float* b2  =(const float*)d_in[16];
    const float* W3  =(const float*)d_in[17];
    const float* b3  =(const float*)d_in[18];
    float* out = (float*)d_out;

    const int attn_smem = (128*68 + 2*64*128) * (int)sizeof(float);  // 100352 B
    const int proj_smem = (128*132 + 128*68) * (int)sizeof(float);   // 102400 B
    cudaFuncSetAttribute(attn2_kernel, cudaFuncAttributeMaxDynamicSharedMemorySize, attn_smem);
    cudaFuncSetAttribute(proj2_kernel, cudaFuncAttributeMaxDynamicSharedMemorySize, proj_smem);

    pack_whh<<<128,256>>>(Whh);
    lstm_kernel<<<NBLK_,256>>>(Xs, Wih, bihp, bhhp, lng, lnb);
    proj2_kernel<<<469,256, proj_smem>>>(WK, nullptr, SL_, 0);   // -> g_Hk
    proj2_kernel<<<47, 256, proj_smem>>>(WQ, tgt,     S_,  1);   // -> g_q
    attn2_kernel<<<dim3(47,NSPLIT_),256, attn_smem>>>(logt, lagb, tgt);
    final_kernel<<<12,256>>>(Xr, W1,b1, W2,b2, W3,b3, out);
}